// round 1
// baseline (speedup 1.0000x reference)
#include <cuda_runtime.h>
#include <math.h>

#define BB 2
#define TT 2048
#define CC 512
#define NB 4
#define QN (NB*CC)   // 2048
#define HALF (CC/2)  // 256

// Scratch (no cudaMalloc allowed)
__device__ float g_Q[BB*TT*QN];  // (B*T, NB*C) roped, pre-scaled by 1/sqrt(C)
__device__ float g_K[BB*TT*CC];  // (B*T, C) roped
__device__ float g_V[BB*TT*QN];  // (B*T, NB*C)
__device__ float g_Y[BB*TT*CC];  // attention output before Wo

// ---------------------------------------------------------------------------
// SGEMM: Out[M,N] = A[M,K] @ W[K,N], row-major. Optional RoPE epilogue + scale.
// BM=128, BN=64, BK=16, 256 threads, 8x4 per thread.
// Requires M%128==0, N%64==0, K%16==0 (true for all launches here).
// ---------------------------------------------------------------------------
template<int DO_ROPE>
__global__ void __launch_bounds__(256) gemm_kernel(
    const float* __restrict__ A, const float* __restrict__ W, float* __restrict__ Out,
    int M, int N, int K,
    const float* __restrict__ cosT, const float* __restrict__ sinT, float scale)
{
    constexpr int BM = 128, BN = 64, BK = 16;
    __shared__ float As[BK][BM];
    __shared__ float Ws[BK][BN];

    const int tid = threadIdx.x;
    const int tx = tid & 15;        // 0..15 -> col group (tx*4)
    const int ty = tid >> 4;        // 0..15 -> row group (ty*8)
    const int rowBase = blockIdx.y * BM;
    const int colBase = blockIdx.x * BN;

    float acc[8][4];
#pragma unroll
    for (int m = 0; m < 8; m++)
#pragma unroll
        for (int n = 0; n < 4; n++) acc[m][n] = 0.f;

    for (int k0 = 0; k0 < K; k0 += BK) {
        // Load A tile (128x16) as float4, store transposed
#pragma unroll
        for (int i = 0; i < 2; i++) {
            int slot = tid + i * 256;          // 0..511
            int r  = slot >> 2;                // 0..127
            int c4 = (slot & 3) * 4;           // 0,4,8,12
            float4 v = *(const float4*)(A + (size_t)(rowBase + r) * K + k0 + c4);
            As[c4 + 0][r] = v.x; As[c4 + 1][r] = v.y;
            As[c4 + 2][r] = v.z; As[c4 + 3][r] = v.w;
        }
        // Load W tile (16x64)
        {
            int rr = tid >> 4;                 // 0..15
            int c4 = (tid & 15) * 4;           // 0..60
            float4 v = *(const float4*)(W + (size_t)(k0 + rr) * N + colBase + c4);
            *(float4*)&Ws[rr][c4] = v;
        }
        __syncthreads();

#pragma unroll
        for (int kk = 0; kk < BK; kk++) {
            float4 a0 = *(float4*)&As[kk][ty * 8];
            float4 a1 = *(float4*)&As[kk][ty * 8 + 4];
            float4 wv = *(float4*)&Ws[kk][tx * 4];
            float ar[8] = {a0.x, a0.y, a0.z, a0.w, a1.x, a1.y, a1.z, a1.w};
            float wr[4] = {wv.x, wv.y, wv.z, wv.w};
#pragma unroll
            for (int m = 0; m < 8; m++)
#pragma unroll
                for (int n = 0; n < 4; n++) acc[m][n] += ar[m] * wr[n];
        }
        __syncthreads();
    }

    const int gc = colBase + tx * 4;
#pragma unroll
    for (int mI = 0; mI < 8; mI++) {
        int gr = rowBase + ty * 8 + mI;
        float o0 = acc[mI][0], o1 = acc[mI][1], o2 = acc[mI][2], o3 = acc[mI][3];
        if (DO_ROPE) {
            int t   = gr & (TT - 1);        // row = b*T + t
            int cin = gc & (CC - 1);        // col within head
            int i0  = cin >> 1;             // pair index (gc%4==0 -> cin even)
            float c0v = cosT[t * HALF + i0],     s0v = sinT[t * HALF + i0];
            float c1v = cosT[t * HALF + i0 + 1], s1v = sinT[t * HALF + i0 + 1];
            float r0 = o0 * c0v - o1 * s0v;
            float r1 = o0 * s0v + o1 * c0v;
            float r2 = o2 * c1v - o3 * s1v;
            float r3 = o2 * s1v + o3 * c1v;
            o0 = r0; o1 = r1; o2 = r2; o3 = r3;
        }
        float4 out4 = make_float4(o0 * scale, o1 * scale, o2 * scale, o3 * scale);
        *(float4*)(Out + (size_t)gr * N + gc) = out4;
    }
}

// ---------------------------------------------------------------------------
// Fused routed attention. 1 warp = 1 query row t; 8 consecutive rows per CTA.
// K tiles (16 x 512 fp32 = 32KB) staged in smem, shared by all 8 warps.
// Online softmax over s with per-step branch max/argmax; V row gathered by LDG.
// ---------------------------------------------------------------------------
__global__ void __launch_bounds__(256) attn_kernel(
    const float* __restrict__ Q, const float* __restrict__ K,
    const float* __restrict__ V, float* __restrict__ Y)
{
    constexpr int SBLK = 16;
    __shared__ float4 ks[SBLK][CC / 4];   // [16][128] float4 = 32KB

    const int tid  = threadIdx.x;
    const int w    = tid >> 5;
    const int lane = tid & 31;
    const int r    = blockIdx.x * 8 + w;  // global row in [0, B*T)
    const int t    = r & (TT - 1);
    const int tmax = (blockIdx.x * 8 + 7) & (TT - 1);

    // Per-lane q fragment: c = jj*128 + lane*4 .. +3
    float4 q[NB][4];
    const float* qp = Q + (size_t)r * QN;
#pragma unroll
    for (int n = 0; n < NB; n++)
#pragma unroll
        for (int jj = 0; jj < 4; jj++)
            q[n][jj] = *(const float4*)(qp + n * CC + jj * 128 + lane * 4);

    float4 acc[4];
#pragma unroll
    for (int jj = 0; jj < 4; jj++) acc[jj] = make_float4(0.f, 0.f, 0.f, 0.f);
    float m = -1e30f, l = 0.f;

    const float* kb = K + (size_t)(r - t) * CC;   // batch base
    const float* vb = V + (size_t)(r - t) * QN;

    for (int s0 = 0; s0 <= tmax; s0 += SBLK) {
        // Cooperative K tile load: 16 rows x 128 float4 = 2048 float4 / 256 thr
#pragma unroll
        for (int i = 0; i < 8; i++) {
            int slot = tid + i * 256;
            int si = slot >> 7, cj = slot & 127;
            ks[si][cj] = *(const float4*)(kb + (size_t)(s0 + si) * CC + cj * 4);
        }
        __syncthreads();

        int send = t - s0; if (send > SBLK - 1) send = SBLK - 1;
        for (int si = 0; si <= send; si++) {
            float4 k4[4];
#pragma unroll
            for (int jj = 0; jj < 4; jj++) k4[jj] = ks[si][jj * 32 + lane];

            float d[NB];
#pragma unroll
            for (int n = 0; n < NB; n++) {
                float s = 0.f;
#pragma unroll
                for (int jj = 0; jj < 4; jj++) {
                    s += q[n][jj].x * k4[jj].x;
                    s += q[n][jj].y * k4[jj].y;
                    s += q[n][jj].z * k4[jj].z;
                    s += q[n][jj].w * k4[jj].w;
                }
                d[n] = s;
            }
#pragma unroll
            for (int off = 16; off > 0; off >>= 1) {
#pragma unroll
                for (int n = 0; n < NB; n++)
                    d[n] += __shfl_xor_sync(0xffffffffu, d[n], off);
            }

            float smax = d[0]; int nsel = 0;
            if (d[1] > smax) { smax = d[1]; nsel = 1; }
            if (d[2] > smax) { smax = d[2]; nsel = 2; }
            if (d[3] > smax) { smax = d[3]; nsel = 3; }

            float mnew  = fmaxf(m, smax);
            float alpha = __expf(m - mnew);
            float p     = __expf(smax - mnew);
            l = l * alpha + p;

            const float4* vr = (const float4*)(vb + (size_t)(s0 + si) * QN + nsel * CC);
#pragma unroll
            for (int jj = 0; jj < 4; jj++) {
                float4 vv = vr[jj * 32 + lane];
                acc[jj].x = acc[jj].x * alpha + p * vv.x;
                acc[jj].y = acc[jj].y * alpha + p * vv.y;
                acc[jj].z = acc[jj].z * alpha + p * vv.z;
                acc[jj].w = acc[jj].w * alpha + p * vv.w;
            }
            m = mnew;
        }
        __syncthreads();
    }

    float inv = 1.f / l;
    float* yp = Y + (size_t)r * CC;
#pragma unroll
    for (int jj = 0; jj < 4; jj++) {
        float4 o = make_float4(acc[jj].x * inv, acc[jj].y * inv,
                               acc[jj].z * inv, acc[jj].w * inv);
        *(float4*)(yp + jj * 128 + lane * 4) = o;
    }
}

// ---------------------------------------------------------------------------
extern "C" void kernel_launch(void* const* d_in, const int* in_sizes, int n_in,
                              void* d_out, int out_size)
{
    const float* a   = (const float*)d_in[0];
    const float* x   = (const float*)d_in[1];
    const float* Wq  = (const float*)d_in[2];
    const float* Wk  = (const float*)d_in[3];
    const float* Wv  = (const float*)d_in[4];
    const float* Wo  = (const float*)d_in[5];
    const float* cosT = (const float*)d_in[6];
    const float* sinT = (const float*)d_in[7];
    float* out = (float*)d_out;

    float* Qb; cudaGetSymbolAddress((void**)&Qb, g_Q);
    float* Kb; cudaGetSymbolAddress((void**)&Kb, g_K);
    float* Vb; cudaGetSymbolAddress((void**)&Vb, g_V);
    float* Yb; cudaGetSymbolAddress((void**)&Yb, g_Y);

    const int M = BB * TT;               // 4096
    const float qscale = 0.04419417382415922f;  // 1/sqrt(512)

    dim3 thr(256);
    // Q = rope(a @ Wq) * 1/sqrt(C)   (4096 x 2048)
    gemm_kernel<1><<<dim3(QN / 64, M / 128), thr>>>(a, Wq, Qb, M, QN, CC, cosT, sinT, qscale);
    // K = rope(x @ Wk)               (4096 x 512)
    gemm_kernel<1><<<dim3(CC / 64, M / 128), thr>>>(x, Wk, Kb, M, CC, CC, cosT, sinT, 1.0f);
    // V = a @ Wv                     (4096 x 2048)
    gemm_kernel<0><<<dim3(QN / 64, M / 128), thr>>>(a, Wv, Vb, M, QN, CC, nullptr, nullptr, 1.0f);
    // Fused routed attention -> Y    (4096 x 512)
    attn_kernel<<<M / 8, thr>>>(Qb, Kb, Vb, Yb);
    // out = Y @ Wo                   (4096 x 512)
    gemm_kernel<0><<<dim3(CC / 64, M / 128), thr>>>(Yb, Wo, out, M, CC, CC, nullptr, nullptr, 1.0f);
}